// round 15
// baseline (speedup 1.0000x reference)
#include <cuda_runtime.h>
#include <cuda_fp16.h>
#include <cstdint>

#define NNODES_MAX 50000
#define HF 128

// U[n][j] = b1[j] + sum_k W1[j][k]*h[n][k],  V[n][j] = sum_k W1[j][128+k]*h[n][k]
__device__ __half g_U[NNODES_MAX * HF];
__device__ __half g_V[NNODES_MAX * HF];

__device__ __forceinline__ uint32_t smem_u32(const void* p) {
    uint32_t a;
    asm("{ .reg .u64 t; cvta.to.shared.u64 t, %1; cvt.u32.u64 %0, t; }"
        : "=r"(a) : "l"(p));
    return a;
}
__device__ __forceinline__ void ldsm4(uint32_t* r, uint32_t addr) {
    asm volatile("ldmatrix.sync.aligned.m8n8.x4.shared.b16 {%0,%1,%2,%3}, [%4];"
                 : "=r"(r[0]), "=r"(r[1]), "=r"(r[2]), "=r"(r[3]) : "r"(addr));
}
__device__ __forceinline__ void mma_f16(float* d, const uint32_t* a, const uint32_t* b) {
    asm volatile(
        "mma.sync.aligned.m16n8k16.row.col.f32.f16.f16.f32 "
        "{%0,%1,%2,%3}, {%4,%5,%6,%7}, {%8,%9}, {%0,%1,%2,%3};"
        : "+f"(d[0]), "+f"(d[1]), "+f"(d[2]), "+f"(d[3])
        : "r"(a[0]), "r"(a[1]), "r"(a[2]), "r"(a[3]), "r"(b[0]), "r"(b[1]));
}

// smem rows: 128 k * 2B = 256B data + 16B pad = 272B -> ldmatrix conflict-free
#define ROWB 272
#define S_A  0
#define S_B  (128 * ROWB)                    // 34816
#define GEMM_SMEM ((128 + 256) * ROWB)       // 104448

// ---------------------------------------------------------------------------
// Kernel 1: persistent node GEMM via mma.sync fp16 (single pass, Ah*Bh).
// Each resident CTA converts B (fp16 of W1) once, then loops over node tiles.
// ---------------------------------------------------------------------------
__global__ __launch_bounds__(512, 1) void node_gemm_mma(
    const float* __restrict__ h,
    const float* __restrict__ W1,
    const float* __restrict__ b1,
    int n_nodes,
    int n_tiles)
{
    extern __shared__ __align__(16) char smc[];
    const uint32_t sb = smem_u32(smc);

    const int tid  = threadIdx.x;
    const int wid  = tid >> 5;
    const int lane = tid & 31;

    const int warp_m = (wid & 3) * 32;    // 4 warps over 128 rows
    const int warp_n = (wid >> 2) * 64;   // 4 warps over 256 cols

    // ---- B tile: convert W1 -> fp16 once per CTA (256 cols x 32 float4) ----
#pragma unroll
    for (int u = tid; u < 8192; u += 512) {
        int c = u >> 5, q = u & 31;
        const float* wp = W1 + (size_t)(c & 127) * 256 + ((c >> 7) << 7) + q * 4;
        float4 v = *(const float4*)wp;
        __half2 h01(__float2half_rn(v.x), __float2half_rn(v.y));
        __half2 h23(__float2half_rn(v.z), __float2half_rn(v.w));
        *(uint2*)(smc + S_B + c * ROWB + q * 8) =
            make_uint2(*(uint32_t*)&h01, *(uint32_t*)&h23);
    }

    const int tig = lane & 3;
    float b1x[8], b1y[8];
#pragma unroll
    for (int nt = 0; nt < 8; nt++) {
        int col = warp_n + nt * 8 + 2 * tig;
        b1x[nt] = (col < 128) ? __ldg(b1 + col)     : 0.f;
        b1y[nt] = (col < 128) ? __ldg(b1 + col + 1) : 0.f;
    }

    for (int tile = blockIdx.x; tile < n_tiles; tile += gridDim.x) {
        const int n0 = tile * 128;
        __syncthreads();   // prior ldmatrix reads done before overwriting A

        // ---- A tile: load h, convert fp16 (8 float4/thread) ----
#pragma unroll
        for (int u = tid; u < 4096; u += 512) {
            int r = u >> 5, q = u & 31;
            int n = n0 + r;
            float4 v = make_float4(0.f, 0.f, 0.f, 0.f);
            if (n < n_nodes)
                v = *(const float4*)(h + (size_t)n * HF + q * 4);
            __half2 h01(__float2half_rn(v.x), __float2half_rn(v.y));
            __half2 h23(__float2half_rn(v.z), __float2half_rn(v.w));
            *(uint2*)(smc + S_A + r * ROWB + q * 8) =
                make_uint2(*(uint32_t*)&h01, *(uint32_t*)&h23);
        }
        __syncthreads();

        float acc[2][8][4];
#pragma unroll
        for (int mt = 0; mt < 2; mt++)
#pragma unroll
            for (int nt = 0; nt < 8; nt++)
#pragma unroll
                for (int i = 0; i < 4; i++) acc[mt][nt][i] = 0.f;

        // ---- MMA sweep: 8 k-steps of 16, single pass ----
#pragma unroll
        for (int ks = 0; ks < 8; ks++) {
            uint32_t ah[2][4];
#pragma unroll
            for (int mt = 0; mt < 2; mt++) {
                int row = warp_m + mt * 16 + (lane & 15);
                uint32_t addr = sb + S_A + row * ROWB + ks * 32 + ((lane >> 4) & 1) * 16;
                ldsm4(ah[mt], addr);
            }
#pragma unroll
            for (int np = 0; np < 4; np++) {
                int r = warp_n + np * 16 + (lane & 7) + ((lane >> 4) & 1) * 8;
                uint32_t addr = sb + S_B + r * ROWB + ks * 32 + ((lane >> 3) & 1) * 16;
                uint32_t bh[4];
                ldsm4(bh, addr);
#pragma unroll
                for (int mt = 0; mt < 2; mt++) {
                    mma_f16(acc[mt][2 * np],     ah[mt], bh);
                    mma_f16(acc[mt][2 * np + 1], ah[mt], bh + 2);
                }
            }
        }

        // ---- epilogue: cols <128 -> U (+b1), >=128 -> V; fp16 stores ----
        const int g = lane >> 2;
#pragma unroll
        for (int nt = 0; nt < 8; nt++) {
            int col = warp_n + nt * 8 + 2 * tig;
            const bool isU = (col < 128);
            __half* __restrict__ dest = isU ? g_U : g_V;
            int cc = isU ? col : (col - 128);
#pragma unroll
            for (int mt = 0; mt < 2; mt++) {
                int r0 = n0 + warp_m + mt * 16 + g;
                if (r0 < n_nodes)
                    *(__half2*)(dest + (size_t)r0 * HF + cc) =
                        __floats2half2_rn(acc[mt][nt][0] + b1x[nt],
                                          acc[mt][nt][1] + b1y[nt]);
                int r1 = r0 + 8;
                if (r1 < n_nodes)
                    *(__half2*)(dest + (size_t)r1 * HF + cc) =
                        __floats2half2_rn(acc[mt][nt][2] + b1x[nt],
                                          acc[mt][nt][3] + b1y[nt]);
            }
        }
    }
}

// ---------------------------------------------------------------------------
// Kernel 2: per-edge  score = W2 . relu(U'[src] + V[dst]) + b2   (b1 in U')
// 2 edges/warp, 16 lanes/edge; low regs -> ~full occupancy (the R13 config:
// occupancy beats per-warp ILP for this gather workload).
// ---------------------------------------------------------------------------
__global__ __launch_bounds__(256) void edge_score_kernel(
    const void* __restrict__ src_raw,
    const void* __restrict__ dst_raw,
    const float* __restrict__ W2,
    const float* __restrict__ b2,
    float* __restrict__ out,
    int n_edges,
    int n_nodes)
{
    __shared__ int s_is64;
    if (threadIdx.x < 32) {
        // Parallel probe: if genuinely int64 (indices < 50000), all high words 0.
        const unsigned int* p = (const unsigned int*)src_raw;
        int slots = n_edges >> 1; if (slots > 32) slots = 32;
        unsigned int hv = (threadIdx.x < slots) ? p[2 * threadIdx.x + 1] : 0u;
        unsigned int any = __ballot_sync(0xffffffffu, hv != 0u);
        if (threadIdx.x == 0) s_is64 = (any == 0u) ? 1 : 0;
    }
    __syncthreads();
    const int is64 = s_is64;

    const int lane = threadIdx.x & 31;
    const int q    = lane >> 4;               // edge slot (0..1)
    const int t    = lane & 15;               // sub-lane within edge (0..15)
    const int warp   = (blockIdx.x * blockDim.x + threadIdx.x) >> 5;
    const int nwarps = (gridDim.x * blockDim.x) >> 5;

    float w2r[8];
    {
        float4 wa = ((const float4*)W2)[2 * t];
        float4 wb = ((const float4*)W2)[2 * t + 1];
        w2r[0] = wa.x; w2r[1] = wa.y; w2r[2] = wa.z; w2r[3] = wa.w;
        w2r[4] = wb.x; w2r[5] = wb.y; w2r[6] = wb.z; w2r[7] = wb.w;
    }
    const float b2v = __ldg(b2);
    const __half2 zero2 = __half2half2(__float2half(0.f));

    const int*       src32 = (const int*)src_raw;
    const int*       dst32 = (const int*)dst_raw;
    const long long* src64 = (const long long*)src_raw;
    const long long* dst64 = (const long long*)dst_raw;

    const int n_iter = (n_edges + 1) >> 1;
    for (int it = warp; it < n_iter; it += nwarps) {
        const int e = it * 2 + q;
        const bool live = (e < n_edges);

        int s = 0, d = 0;
        if (live) {
            if (is64) {
                s = (int)__ldg(src64 + e);
                d = (int)__ldg(dst64 + e);
            } else {
                s = __ldg(src32 + e);
                d = __ldg(dst32 + e);
            }
        }
        unsigned int su = ((unsigned int)s < (unsigned int)n_nodes) ? (unsigned int)s : 0u;
        unsigned int du = ((unsigned int)d < (unsigned int)n_nodes) ? (unsigned int)d : 0u;

        uint4 ua = ((const uint4*)(g_U + (size_t)su * HF))[t];
        uint4 va = ((const uint4*)(g_V + (size_t)du * HF))[t];

        const __half2* up = (const __half2*)&ua;
        const __half2* vp = (const __half2*)&va;
        float acc = 0.f;
#pragma unroll
        for (int i = 0; i < 4; i++) {
            __half2 z = __hmax2(__hadd2(up[i], vp[i]), zero2);
            float2 zf = __half22float2(z);
            acc = fmaf(zf.x, w2r[2 * i + 0], acc);
            acc = fmaf(zf.y, w2r[2 * i + 1], acc);
        }
        acc += __shfl_xor_sync(0xffffffffu, acc, 1);
        acc += __shfl_xor_sync(0xffffffffu, acc, 2);
        acc += __shfl_xor_sync(0xffffffffu, acc, 4);
        acc += __shfl_xor_sync(0xffffffffu, acc, 8);

        if (t == 0 && live) out[e] = acc + b2v;
    }
}

// ---------------------------------------------------------------------------
// Launch
// ---------------------------------------------------------------------------
extern "C" void kernel_launch(void* const* d_in, const int* in_sizes, int n_in,
                              void* d_out, int out_size)
{
    const float* h   = (const float*)d_in[0];
    const void*  src = d_in[1];
    const void*  dst = d_in[2];
    const float* W1  = (const float*)d_in[3];
    const float* b1  = (const float*)d_in[4];
    const float* W2  = (const float*)d_in[5];
    const float* b2  = (const float*)d_in[6];
    float* out = (float*)d_out;

    const int n_nodes = in_sizes[0] / HF;
    const int n_edges = in_sizes[1];
    const int n_tiles = (n_nodes + 127) / 128;
    const int grid    = (n_tiles < 148) ? n_tiles : 148;

    cudaFuncSetAttribute(node_gemm_mma,
                         cudaFuncAttributeMaxDynamicSharedMemorySize, GEMM_SMEM);

    node_gemm_mma<<<grid, 512, GEMM_SMEM>>>(h, W1, b1, n_nodes, n_tiles);
    edge_score_kernel<<<1184, 256>>>(src, dst, W2, b2, out, n_edges, n_nodes);
}